// round 7
// baseline (speedup 1.0000x reference)
#include <cuda_runtime.h>
#include <cuda_fp16.h>
#include <math_constants.h>

#define NUM_CODES 2560
#define DIM       128
#define N_TOKENS  65536
#define TOT_ELEMS 8388608
#define TPC       256          // tokens per CTA (tensor pass)
#define CPC       64           // codes per chunk (tensor pass)
#define N_CHUNKS  40
#define NSTAGE    3
#define THRESH    4e-4f        // > 2*(|zl.w|+|z.wl| bound) + ulp(256), with margin

#define RS          272                    // padded row stride bytes (128 fp16 = 256B + 16 pad)
#define STAGE_B     (64 * RS)              // 17408
#define OFF_BST     0                      // B stages / A fp16 temp (aliased)
#define OFF_EN      69632                  // = 256*RS (A temp size dominates 3*STAGE_B)
#define OFF_ZN      (OFF_EN + NUM_CODES * 4)
#define SMEM_TENSOR (OFF_ZN + 1024)

// recheck (R1-core) smem layout, in floats
#define ZSTR        132
#define RT          16
#define R_CHUNK     256
#define R_NCH       10

__device__ __align__(16) float  g_enorm[NUM_CODES];
__device__ __align__(16) __half g_wh16[NUM_CODES * DIM];   // fp16(w * 4096)
__device__ int    g_inds[N_TOKENS];
__device__ int    g_list[N_TOKENS];
__device__ int    g_nflag;
__device__ double g_s1, g_s3;

// ---------- helpers ----------
__device__ __forceinline__ unsigned smem_u32(const void* p) {
    unsigned a;
    asm("{ .reg .u64 t; cvta.to.shared.u64 t, %1; cvt.u32.u64 %0, t; }" : "=r"(a) : "l"(p));
    return a;
}
__device__ __forceinline__ unsigned lds32(unsigned a) {
    unsigned v;
    asm volatile("ld.shared.b32 %0, [%1];" : "=r"(v) : "r"(a));
    return v;
}
__device__ __forceinline__ float2 lds64f(unsigned a) {
    float2 v;
    asm volatile("ld.shared.v2.f32 {%0, %1}, [%2];" : "=f"(v.x), "=f"(v.y) : "r"(a));
    return v;
}
// fp16 tensor-core mma: D(16x8,f32) += A(16x16,f16,row) * B(16x8,f16,col)
__device__ __forceinline__ void mma_f16(float* c, const unsigned* a,
                                        unsigned b0, unsigned b1) {
    asm volatile(
        "mma.sync.aligned.m16n8k16.row.col.f32.f16.f16.f32 "
        "{%0,%1,%2,%3}, {%4,%5,%6,%7}, {%8,%9}, {%0,%1,%2,%3};"
        : "+f"(c[0]), "+f"(c[1]), "+f"(c[2]), "+f"(c[3])
        : "r"(a[0]), "r"(a[1]), "r"(a[2]), "r"(a[3]), "r"(b0), "r"(b1));
}
__device__ __forceinline__ unsigned long long ffma2(unsigned long long a,
                                                    unsigned long long b,
                                                    unsigned long long c) {
    unsigned long long d;
    asm("fma.rn.f32x2 %0, %1, %2, %3;" : "=l"(d) : "l"(a), "l"(b), "l"(c));
    return d;
}
__device__ __forceinline__ void unpack2(unsigned long long p, float& lo, float& hi) {
    asm("mov.b64 {%0, %1}, %2;" : "=f"(lo), "=f"(hi) : "l"(p));
}

// ---------- prep: enorm + fp16(w*4096) ----------
__global__ void vq_prep(const float* __restrict__ w) {
    int gtid = blockIdx.x * blockDim.x + threadIdx.x;
    if (gtid == 0) { g_s1 = 0.0; g_s3 = 0.0; g_nflag = 0; }
    int gw = gtid >> 5, lane = threadIdx.x & 31;
    if (gw < NUM_CODES) {
        const float* row = w + (size_t)gw * DIM;
        float s = 0.0f;
        #pragma unroll
        for (int k = lane; k < DIM; k += 32) {
            float v = row[k];
            s = __fadd_rn(s, __fmul_rn(v, v));
        }
        #pragma unroll
        for (int off = 16; off > 0; off >>= 1) s += __shfl_xor_sync(~0u, s, off);
        if (lane == 0) g_enorm[gw] = s;
    }
    int stride = gridDim.x * blockDim.x;
    for (int i = gtid; i < NUM_CODES * DIM; i += stride)
        g_wh16[i] = __float2half_rn(w[i] * 4096.0f);   // *2^12 exact
}

// ---------- tensor pass ----------
__device__ __forceinline__ void issue_chunk(unsigned sb, int tid, int cn, int st) {
    const uint4* gh = ((const uint4*)g_wh16) + (size_t)cn * 1024;
    unsigned base = sb + OFF_BST + st * STAGE_B;
    #pragma unroll
    for (int i = 0; i < 4; i++) {
        int f = tid + i * 256;            // 0..1023: row = f>>4, 16B col = f&15
        unsigned d = base + (f >> 4) * RS + (f & 15) * 16;
        asm volatile("cp.async.cg.shared.global [%0], [%1], 16;" :: "r"(d), "l"(gh + f));
    }
}

__global__ void __launch_bounds__(256, 1)
vq_tensor(const float* __restrict__ batch) {
    extern __shared__ char smem[];
    const unsigned sb = smem_u32(smem);
    float* zn_s = (float*)(smem + OFF_ZN);

    const int tid = threadIdx.x, wid = tid >> 5, lane = tid & 31;
    const int n0 = blockIdx.x * TPC, b = n0 >> 12, hw0 = n0 & 4095;
    const float* zbase = batch + (size_t)b * (DIM * 4096) + hw0;

    // prologue: thread tid = token tid: znorm (R1 order) + fp16(z*16) into A temp
    {
        const float* zp = zbase + tid;
        float acc = 0.0f;
        #pragma unroll 4
        for (int c = 0; c < DIM; c += 2) {
            float z0 = zp[(size_t)c * 4096];
            float z1 = zp[(size_t)(c + 1) * 4096];
            acc = __fadd_rn(acc, __fmul_rn(z0, z0));
            acc = __fadd_rn(acc, __fmul_rn(z1, z1));
            __half h0 = __float2half_rn(z0 * 16.0f);   // *2^4 exact
            __half h1 = __float2half_rn(z1 * 16.0f);
            unsigned hp = (unsigned)__half_as_ushort(h0) |
                          ((unsigned)__half_as_ushort(h1) << 16);
            *(unsigned*)(smem + OFF_BST + tid * RS + c * 2) = hp;
        }
        zn_s[tid] = acc;
    }
    for (int i = tid; i < NUM_CODES; i += 256)
        ((float*)(smem + OFF_EN))[i] = g_enorm[i];
    __syncthreads();

    // chunk-invariant A fragments -> registers
    const unsigned Rb = wid * 32 + (lane >> 2);
    const unsigned Cb = (lane & 3) * 2;
    unsigned Ah[2][8][4];
    #pragma unroll
    for (int mt = 0; mt < 2; mt++)
        #pragma unroll
        for (int ks = 0; ks < 8; ks++) {
            unsigned a = sb + OFF_BST + (Rb + mt * 16) * RS + (ks * 16 + Cb) * 2;
            Ah[mt][ks][0] = lds32(a);
            Ah[mt][ks][1] = lds32(a + 8 * RS);
            Ah[mt][ks][2] = lds32(a + 16);
            Ah[mt][ks][3] = lds32(a + 8 * RS + 16);
        }
    float znr[4];
    #pragma unroll
    for (int j = 0; j < 4; j++) znr[j] = zn_s[Rb + j * 8];
    __syncthreads();   // A temp fully consumed before B stages overwrite it

    issue_chunk(sb, tid, 0, 0);
    asm volatile("cp.async.commit_group;" ::: "memory");
    issue_chunk(sb, tid, 1, 1);
    asm volatile("cp.async.commit_group;" ::: "memory");
    issue_chunk(sb, tid, 2, 2);
    asm volatile("cp.async.commit_group;" ::: "memory");

    float acc[2][8][4];
    #pragma unroll
    for (int mt = 0; mt < 2; mt++)
        #pragma unroll
        for (int nt = 0; nt < 8; nt++)
            #pragma unroll
            for (int q = 0; q < 4; q++) acc[mt][nt][q] = 0.0f;
    float bv1[4] = {CUDART_INF_F, CUDART_INF_F, CUDART_INF_F, CUDART_INF_F};
    float bv2[4] = {CUDART_INF_F, CUDART_INF_F, CUDART_INF_F, CUDART_INF_F};
    int   bi1[4] = {0, 0, 0, 0};

    const unsigned bfrag_base = sb + OFF_BST + (lane >> 2) * RS + Cb * 2;
    const float DS = -3.0517578125e-05f;   // -2 * 2^-16 (undo 16*4096 scaling), exact

    for (int cn = 0; cn < N_CHUNKS; cn++) {
        asm volatile("cp.async.wait_group 2;" ::: "memory");
        __syncthreads();
        const unsigned sbase = (unsigned)(cn % NSTAGE) * STAGE_B;

        #pragma unroll
        for (int ks = 0; ks < 8; ks++) {
            #pragma unroll
            for (int nt = 0; nt < 8; nt++) {
                unsigned ba = bfrag_base + sbase + nt * 8 * RS + ks * 32;
                unsigned b0 = lds32(ba), b1 = lds32(ba + 16);
                mma_f16(acc[0][nt], Ah[0][ks], b0, b1);
                mma_f16(acc[1][nt], Ah[1][ks], b0, b1);
            }
        }
        __syncthreads();
        if (cn + NSTAGE < N_CHUNKS) issue_chunk(sb, tid, cn + NSTAGE, cn % NSTAGE);
        asm volatile("cp.async.commit_group;" ::: "memory");

        // fused distance + best/second-best tracking; reset acc
        #pragma unroll
        for (int nt = 0; nt < 8; nt++) {
            const int code0 = cn * CPC + nt * 8 + (int)Cb;
            float2 e = lds64f(sb + OFF_EN + (unsigned)code0 * 4);
            #pragma unroll
            for (int mt = 0; mt < 2; mt++) {
                float d0 = fmaf(DS, acc[mt][nt][0], znr[2 * mt] + e.x);
                float d1 = fmaf(DS, acc[mt][nt][1], znr[2 * mt] + e.y);
                float d2 = fmaf(DS, acc[mt][nt][2], znr[2 * mt + 1] + e.x);
                float d3 = fmaf(DS, acc[mt][nt][3], znr[2 * mt + 1] + e.y);
                int x = 2 * mt, y = 2 * mt + 1;
                if (d0 < bv1[x]) { bv2[x] = bv1[x]; bv1[x] = d0; bi1[x] = code0; }
                else if (d0 < bv2[x]) bv2[x] = d0;
                if (d1 < bv1[x]) { bv2[x] = bv1[x]; bv1[x] = d1; bi1[x] = code0 + 1; }
                else if (d1 < bv2[x]) bv2[x] = d1;
                if (d2 < bv1[y]) { bv2[y] = bv1[y]; bv1[y] = d2; bi1[y] = code0; }
                else if (d2 < bv2[y]) bv2[y] = d2;
                if (d3 < bv1[y]) { bv2[y] = bv1[y]; bv1[y] = d3; bi1[y] = code0 + 1; }
                else if (d3 < bv2[y]) bv2[y] = d3;
                acc[mt][nt][0] = 0.0f; acc[mt][nt][1] = 0.0f;
                acc[mt][nt][2] = 0.0f; acc[mt][nt][3] = 0.0f;
            }
        }
    }

    // quad merge of (best, second-best); flag near-ties for exact recheck
    #pragma unroll
    for (int j = 0; j < 4; j++) {
        float v1 = bv1[j], v2 = bv2[j];
        int   i1 = bi1[j];
        #pragma unroll
        for (int off = 1; off <= 2; off <<= 1) {
            float o1  = __shfl_xor_sync(~0u, v1, off);
            int   o1i = __shfl_xor_sync(~0u, i1, off);
            float o2  = __shfl_xor_sync(~0u, v2, off);
            if (o1 < v1 || (o1 == v1 && o1i < i1)) {
                v2 = fminf(v1, o2); v1 = o1; i1 = o1i;
            } else {
                v2 = fminf(v2, o1);
            }
        }
        if ((lane & 3) == 0) {
            int token = n0 + (int)Rb + j * 8;
            g_inds[token] = i1;
            if (v2 - v1 < THRESH) {
                int p = atomicAdd(&g_nflag, 1);
                g_list[p] = token;
            }
        }
    }
}

// ---------- recheck: verbatim Round-1 numerics for flagged tokens ----------
__global__ void __launch_bounds__(256, 1)
vq_recheck(const float* __restrict__ batch, const float* __restrict__ w) {
    const int base = blockIdx.x * RT;
    const int nf = *(volatile int*)&g_nflag;
    if (base >= nf) return;

    extern __shared__ float sm[];
    float* zs = sm;                               // 16*132
    float* ws = sm + RT * ZSTR;                   // 256*132
    float* zn = ws + R_CHUNK * ZSTR;              // 16
    float* en = zn + RT;                          // 256
    int*   tk = (int*)(en + R_CHUNK);             // 16
    int*   tb = tk + RT;                          // 16
    float* rv = ws;                               // reduce alias
    int*   ri = (int*)(ws + 512);

    const int tid = threadIdx.x;
    if (tid < RT) {
        int t = (base + tid < nf) ? g_list[base + tid] : -1;
        tk[tid] = t;
        int tt = (t >= 0) ? t : 0;
        tb[tid] = (tt >> 12) * (DIM * 4096) + (tt & 4095);
    }
    __syncthreads();

    for (int idx = tid; idx < RT * DIM; idx += 256) {
        int t = idx & 15, c = idx >> 4;
        zs[t * ZSTR + c] = batch[(size_t)tb[t] + (size_t)c * 4096];
    }
    __syncthreads();

    if (tid < RT) {
        float s = 0.0f;
        const float* zr = zs + tid * ZSTR;
        #pragma unroll 8
        for (int c = 0; c < DIM; c++)
            s = __fadd_rn(s, __fmul_rn(zr[c], zr[c]));
        zn[tid] = s;
    }
    __syncthreads();

    const int tg = tid & 7;
    const int cg = tid >> 3;

    int zrow[2], wrow[8];
    zrow[0] = tg * ZSTR; zrow[1] = (tg + 8) * ZSTR;
    #pragma unroll
    for (int j = 0; j < 8; j++) wrow[j] = (cg + 32 * j) * ZSTR;
    float znrv[2] = {zn[tg], zn[tg + 8]};

    float bestv[2] = {CUDART_INF_F, CUDART_INF_F};
    int   besti[2] = {0, 0};

    for (int chunk = 0; chunk < R_NCH; chunk++) {
        const int cb = chunk * R_CHUNK;
        __syncthreads();
        for (int f = tid; f < R_CHUNK * 32; f += 256) {
            int code = f >> 5, d4 = f & 31;
            float4 v = ((const float4*)(w + (size_t)(cb + code) * DIM))[d4];
            *(float4*)&ws[code * ZSTR + d4 * 4] = v;
        }
        if (tid < R_CHUNK) en[tid] = g_enorm[cb + tid];
        __syncthreads();

        unsigned long long acc[2][8];
        #pragma unroll
        for (int i = 0; i < 2; i++)
            #pragma unroll
            for (int j = 0; j < 8; j++) acc[i][j] = 0ull;

        #pragma unroll 2
        for (int d4 = 0; d4 < DIM / 4; d4++) {
            unsigned long long za0[2], za1[2];
            #pragma unroll
            for (int i = 0; i < 2; i++) {
                ulonglong2 v = *(const ulonglong2*)(zs + zrow[i] + d4 * 4);
                za0[i] = v.x; za1[i] = v.y;
            }
            #pragma unroll
            for (int j = 0; j < 8; j++) {
                ulonglong2 wv = *(const ulonglong2*)(ws + wrow[j] + d4 * 4);
                #pragma unroll
                for (int i = 0; i < 2; i++) {
                    acc[i][j] = ffma2(za0[i], wv.x, acc[i][j]);
                    acc[i][j] = ffma2(za1[i], wv.y, acc[i][j]);
                }
            }
        }
        #pragma unroll
        for (int j = 0; j < 8; j++) {
            const int code = cb + cg + 32 * j;
            const float ec = en[cg + 32 * j];
            #pragma unroll
            for (int i = 0; i < 2; i++) {
                float lo, hi;
                unpack2(acc[i][j], lo, hi);
                float dot = lo + hi;
                float s   = znrv[i] + ec;
                float dis = fmaf(-2.0f, dot, s);
                if (dis < bestv[i]) { bestv[i] = dis; besti[i] = code; }
            }
        }
    }

    __syncthreads();
    #pragma unroll
    for (int i = 0; i < 2; i++) {
        int t = tg + 8 * i;
        rv[t * 32 + cg] = bestv[i];
        ri[t * 32 + cg] = besti[i];
    }
    __syncthreads();
    if (tid < RT) {
        float bvv = rv[tid * 32];
        int   bii = ri[tid * 32];
        for (int c2 = 1; c2 < 32; c2++) {
            float v = rv[tid * 32 + c2];
            int  ii = ri[tid * 32 + c2];
            if (v < bvv || (v == bvv && ii < bii)) { bvv = v; bii = ii; }
        }
        if (tk[tid] >= 0) g_inds[tk[tid]] = bii;
    }
}

// ---------- output + loss: smem-staged gather, all-coalesced, fp32 partials ----------
__global__ void __launch_bounds__(256, 1)
vq_output(const float* __restrict__ batch, const float* __restrict__ w,
          float* __restrict__ out) {
    __shared__ float qsT[128 * 66];    // [c][token], stride 66 (even, 8B-aligned rows)
    __shared__ int   si[64];
    __shared__ float red[512];

    const int tid = threadIdx.x, wid = tid >> 5, lane = tid & 31;
    const int n0 = blockIdx.x * 64, b = n0 >> 12, hw0 = n0 & 4095;

    if (tid < 64) si[tid] = g_inds[n0 + tid];
    __syncthreads();

    // stage 1: gather 64 code rows (coalesced float4), store transposed
    const float4* w4 = (const float4*)w;
    #pragma unroll
    for (int k = 0; k < 8; k++) {
        int f = tid + k * 256;            // 0..2047: r = f>>5, c4 = f&31
        int r = f >> 5, c4 = f & 31;
        float4 v = __ldg(&w4[(size_t)si[r] * 32 + c4]);
        int cb = c4 * 4;
        qsT[(cb + 0) * 66 + r] = v.x;
        qsT[(cb + 1) * 66 + r] = v.y;
        qsT[(cb + 2) * 66 + r] = v.z;
        qsT[(cb + 3) * 66 + r] = v.w;
    }
    __syncthreads();

    // stage 2: per warp-iteration one dim c over 64 tokens (float2 coalesced)
    float s1 = 0.0f, s3 = 0.0f;
    #pragma unroll 4
    for (int it = 0; it < 16; it++) {
        int c = wid * 16 + it;
        size_t go = ((size_t)(b * 128 + c)) * 4096 + hw0 + 2 * lane;
        float2 z2 = *(const float2*)(batch + go);
        float q0 = qsT[c * 66 + 2 * lane];
        float q1 = qsT[c * 66 + 2 * lane + 1];
        float dq0 = q0 - z2.x, dq1 = q1 - z2.y;
        float ov0 = z2.x + dq0, ov1 = z2.y + dq1;
        float d30 = z2.x - ov0, d31 = z2.y - ov1;
        *(float2*)(out + go) = make_float2(ov0, ov1);
        s1 += dq0 * dq0 + dq1 * dq1;
        s3 += d30 * d30 + d31 * d31;
    }
    red[tid] = s1; red[256 + tid] = s3;
    __syncthreads();
    #pragma unroll
    for (int st = 128; st > 0; st >>= 1) {
        if (tid < st) { red[tid] += red[tid + st]; red[256 + tid] += red[256 + tid + st]; }
        __syncthreads();
    }
    if (tid == 0) {
        atomicAdd(&g_s1, (double)red[0]);
        atomicAdd(&g_s3, (double)red[256]);
    }
}

// ---------- finalize ----------
__global__ void vq_finalize(float* __restrict__ out, int out_size) {
    if (out_size <= TOT_ELEMS) return;
    const double inv = 1.0 / (double)TOT_ELEMS;
    float t1 = (float)(g_s1 * inv);
    float t3 = (float)(g_s3 * inv);
    out[TOT_ELEMS] = (t1 + t1) + t3 * 50.0f;
}

// ---------- launch ----------
extern "C" void kernel_launch(void* const* d_in, const int* in_sizes, int n_in,
                              void* d_out, int out_size) {
    const float* batch = (const float*)d_in[0];
    const float* wq    = (const float*)d_in[1];
    if (n_in >= 2 && in_sizes[0] == NUM_CODES * DIM) {
        const float* t = batch; batch = wq; wq = t;
    }
    float* out = (float*)d_out;

    const int SMEM_RECHECK = (RT * ZSTR + R_CHUNK * ZSTR + RT + R_CHUNK) * 4 + 128;

    cudaFuncSetAttribute(vq_tensor, cudaFuncAttributeMaxDynamicSharedMemorySize,
                         SMEM_TENSOR);
    cudaFuncSetAttribute(vq_recheck, cudaFuncAttributeMaxDynamicSharedMemorySize,
                         SMEM_RECHECK);

    vq_prep<<<320, 256>>>(wq);
    vq_tensor<<<N_TOKENS / TPC, 256, SMEM_TENSOR>>>(batch);
    vq_recheck<<<N_TOKENS / RT, 256, SMEM_RECHECK>>>(batch, wq);
    vq_output<<<N_TOKENS / 64, 256>>>(batch, wq, out);
    vq_finalize<<<1, 1>>>(out, out_size);
}

// round 8
// speedup vs baseline: 1.4583x; 1.4583x over previous
#include <cuda_runtime.h>
#include <cuda_fp16.h>
#include <math_constants.h>

#define NUM_CODES 2560
#define DIM       128
#define N_TOKENS  65536
#define TOT_ELEMS 8388608
#define TPC       256
#define CPC       64
#define N_CHUNKS  40
#define NSTAGE    3

#define RS          272
#define STAGE_B     (64 * RS)
#define OFF_BST     0
#define OFF_EN      69632                  // 256*RS (A temp) dominates 3*STAGE_B
#define OFF_ZN      (OFF_EN + NUM_CODES * 4)
#define SMEM_TENSOR (OFF_ZN + 1024)

#define ZSTR        132
#define RT          16
#define R_CHUNK     256
#define R_NCH       10

__device__ __align__(16) float  g_enorm[NUM_CODES];
__device__ __align__(16) __half g_wh16[NUM_CODES * DIM];   // fp16(w * 4096)
__device__ int    g_enmax_i = 0;
__device__ int    g_inds[N_TOKENS];
__device__ int    g_listA[N_TOKENS];
__device__ int    g_i2a[N_TOKENS];
__device__ int    g_listB[N_TOKENS];
__device__ int    g_nA, g_nB;
__device__ double g_s1, g_s3;

// ---------- helpers ----------
__device__ __forceinline__ unsigned smem_u32(const void* p) {
    unsigned a;
    asm("{ .reg .u64 t; cvta.to.shared.u64 t, %1; cvt.u32.u64 %0, t; }" : "=r"(a) : "l"(p));
    return a;
}
__device__ __forceinline__ unsigned lds32(unsigned a) {
    unsigned v;
    asm volatile("ld.shared.b32 %0, [%1];" : "=r"(v) : "r"(a));
    return v;
}
__device__ __forceinline__ float2 lds64f(unsigned a) {
    float2 v;
    asm volatile("ld.shared.v2.f32 {%0, %1}, [%2];" : "=f"(v.x), "=f"(v.y) : "r"(a));
    return v;
}
__device__ __forceinline__ void mma_f16(float* c, const unsigned* a,
                                        unsigned b0, unsigned b1) {
    asm volatile(
        "mma.sync.aligned.m16n8k16.row.col.f32.f16.f16.f32 "
        "{%0,%1,%2,%3}, {%4,%5,%6,%7}, {%8,%9}, {%0,%1,%2,%3};"
        : "+f"(c[0]), "+f"(c[1]), "+f"(c[2]), "+f"(c[3])
        : "r"(a[0]), "r"(a[1]), "r"(a[2]), "r"(a[3]), "r"(b0), "r"(b1));
}
__device__ __forceinline__ unsigned long long ffma2(unsigned long long a,
                                                    unsigned long long b,
                                                    unsigned long long c) {
    unsigned long long d;
    asm("fma.rn.f32x2 %0, %1, %2, %3;" : "=l"(d) : "l"(a), "l"(b), "l"(c));
    return d;
}
__device__ __forceinline__ void unpack2(unsigned long long p, float& lo, float& hi) {
    asm("mov.b64 {%0, %1}, %2;" : "=f"(lo), "=f"(hi) : "l"(p));
}

// ---------- prep: enorm (+max) + fp16(w*4096) ----------
__global__ void vq_prep(const float* __restrict__ w) {
    int gtid = blockIdx.x * blockDim.x + threadIdx.x;
    if (gtid == 0) { g_s1 = 0.0; g_s3 = 0.0; g_nA = 0; g_nB = 0; }
    int gw = gtid >> 5, lane = threadIdx.x & 31;
    if (gw < NUM_CODES) {
        const float* row = w + (size_t)gw * DIM;
        float s = 0.0f;
        #pragma unroll
        for (int k = lane; k < DIM; k += 32) {
            float v = row[k];
            s = __fadd_rn(s, __fmul_rn(v, v));
        }
        #pragma unroll
        for (int off = 16; off > 0; off >>= 1) s += __shfl_xor_sync(~0u, s, off);
        if (lane == 0) {
            g_enorm[gw] = s;
            atomicMax(&g_enmax_i, __float_as_int(s));   // positive: int-order == float-order
        }
    }
    int stride = gridDim.x * blockDim.x;
    for (int i = gtid; i < NUM_CODES * DIM; i += stride)
        g_wh16[i] = __float2half_rn(w[i] * 4096.0f);
}

// ---------- tensor pass ----------
__device__ __forceinline__ void issue_chunk(unsigned sb, int tid, int cn, int st) {
    const uint4* gh = ((const uint4*)g_wh16) + (size_t)cn * 1024;
    unsigned base = sb + OFF_BST + st * STAGE_B;
    #pragma unroll
    for (int i = 0; i < 4; i++) {
        int f = tid + i * 256;
        unsigned d = base + (f >> 4) * RS + (f & 15) * 16;
        asm volatile("cp.async.cg.shared.global [%0], [%1], 16;" :: "r"(d), "l"(gh + f));
    }
}

__global__ void __launch_bounds__(256, 1)
vq_tensor(const float* __restrict__ batch) {
    extern __shared__ char smem[];
    const unsigned sb = smem_u32(smem);
    float* zn_s = (float*)(smem + OFF_ZN);

    const int tid = threadIdx.x, wid = tid >> 5, lane = tid & 31;
    const int n0 = blockIdx.x * TPC, b = n0 >> 12, hw0 = n0 & 4095;
    const float* zbase = batch + (size_t)b * (DIM * 4096) + hw0;
    const float enmax = __int_as_float(g_enmax_i);

    // prologue: token tid: znorm (R1 order) + fp16(z*16) into A temp
    {
        const float* zp = zbase + tid;
        float acc = 0.0f;
        #pragma unroll 4
        for (int c = 0; c < DIM; c += 2) {
            float z0 = zp[(size_t)c * 4096];
            float z1 = zp[(size_t)(c + 1) * 4096];
            acc = __fadd_rn(acc, __fmul_rn(z0, z0));
            acc = __fadd_rn(acc, __fmul_rn(z1, z1));
            __half h0 = __float2half_rn(z0 * 16.0f);
            __half h1 = __float2half_rn(z1 * 16.0f);
            unsigned hp = (unsigned)__half_as_ushort(h0) |
                          ((unsigned)__half_as_ushort(h1) << 16);
            *(unsigned*)(smem + OFF_BST + tid * RS + c * 2) = hp;
        }
        zn_s[tid] = acc;
    }
    for (int i = tid; i < NUM_CODES; i += 256)
        ((float*)(smem + OFF_EN))[i] = g_enorm[i];
    __syncthreads();

    const unsigned Rb = wid * 32 + (lane >> 2);
    const unsigned Cb = (lane & 3) * 2;
    unsigned Ah[2][8][4];
    #pragma unroll
    for (int mt = 0; mt < 2; mt++)
        #pragma unroll
        for (int ks = 0; ks < 8; ks++) {
            unsigned a = sb + OFF_BST + (Rb + mt * 16) * RS + (ks * 16 + Cb) * 2;
            Ah[mt][ks][0] = lds32(a);
            Ah[mt][ks][1] = lds32(a + 8 * RS);
            Ah[mt][ks][2] = lds32(a + 16);
            Ah[mt][ks][3] = lds32(a + 8 * RS + 16);
        }
    float znr[4];
    #pragma unroll
    for (int j = 0; j < 4; j++) znr[j] = zn_s[Rb + j * 8];
    __syncthreads();

    issue_chunk(sb, tid, 0, 0);
    asm volatile("cp.async.commit_group;" ::: "memory");
    issue_chunk(sb, tid, 1, 1);
    asm volatile("cp.async.commit_group;" ::: "memory");
    issue_chunk(sb, tid, 2, 2);
    asm volatile("cp.async.commit_group;" ::: "memory");

    float acc[2][8][4];
    #pragma unroll
    for (int mt = 0; mt < 2; mt++)
        #pragma unroll
        for (int nt = 0; nt < 8; nt++)
            #pragma unroll
            for (int q = 0; q < 4; q++) acc[mt][nt][q] = 0.0f;

    float v1[4], v2[4], v3[4];
    int   i1[4], i2[4];
    #pragma unroll
    for (int j = 0; j < 4; j++) {
        v1[j] = CUDART_INF_F; v2[j] = CUDART_INF_F; v3[j] = CUDART_INF_F;
        i1[j] = 0; i2[j] = 0;
    }

    const unsigned bfrag_base = sb + OFF_BST + (lane >> 2) * RS + Cb * 2;
    const float DS = -3.0517578125e-05f;   // -2 * 2^-16

    #define UPD(sl, dv, cd) \
        if ((dv) < v1[sl]) { v3[sl]=v2[sl]; v2[sl]=v1[sl]; i2[sl]=i1[sl]; v1[sl]=(dv); i1[sl]=(cd); } \
        else if ((dv) < v2[sl]) { v3[sl]=v2[sl]; v2[sl]=(dv); i2[sl]=(cd); } \
        else if ((dv) < v3[sl]) v3[sl]=(dv);

    for (int cn = 0; cn < N_CHUNKS; cn++) {
        asm volatile("cp.async.wait_group 2;" ::: "memory");
        __syncthreads();
        const unsigned sbase = (unsigned)(cn % NSTAGE) * STAGE_B;

        #pragma unroll
        for (int ks = 0; ks < 8; ks++) {
            #pragma unroll
            for (int nt = 0; nt < 8; nt++) {
                unsigned ba = bfrag_base + sbase + nt * 8 * RS + ks * 32;
                unsigned b0 = lds32(ba), b1 = lds32(ba + 16);
                mma_f16(acc[0][nt], Ah[0][ks], b0, b1);
                mma_f16(acc[1][nt], Ah[1][ks], b0, b1);
            }
        }
        __syncthreads();
        if (cn + NSTAGE < N_CHUNKS) issue_chunk(sb, tid, cn + NSTAGE, cn % NSTAGE);
        asm volatile("cp.async.commit_group;" ::: "memory");

        #pragma unroll
        for (int nt = 0; nt < 8; nt++) {
            const int code0 = cn * CPC + nt * 8 + (int)Cb;
            float2 e = lds64f(sb + OFF_EN + (unsigned)code0 * 4);
            #pragma unroll
            for (int mt = 0; mt < 2; mt++) {
                float d0 = fmaf(DS, acc[mt][nt][0], znr[2 * mt] + e.x);
                float d1 = fmaf(DS, acc[mt][nt][1], znr[2 * mt] + e.y);
                float d2 = fmaf(DS, acc[mt][nt][2], znr[2 * mt + 1] + e.x);
                float d3 = fmaf(DS, acc[mt][nt][3], znr[2 * mt + 1] + e.y);
                UPD(2 * mt,     d0, code0);
                UPD(2 * mt,     d1, code0 + 1);
                UPD(2 * mt + 1, d2, code0);
                UPD(2 * mt + 1, d3, code0 + 1);
                acc[mt][nt][0] = 0.0f; acc[mt][nt][1] = 0.0f;
                acc[mt][nt][2] = 0.0f; acc[mt][nt][3] = 0.0f;
            }
        }
    }
    #undef UPD

    // quad merge of top-3 + classify
    #pragma unroll
    for (int j = 0; j < 4; j++) {
        float a1 = v1[j], a2 = v2[j], a3 = v3[j];
        int   b1 = i1[j], b2 = i2[j];
        #pragma unroll
        for (int off = 1; off <= 2; off <<= 1) {
            float o1 = __shfl_xor_sync(~0u, a1, off);
            int   p1 = __shfl_xor_sync(~0u, b1, off);
            float o2 = __shfl_xor_sync(~0u, a2, off);
            int   p2 = __shfl_xor_sync(~0u, b2, off);
            float o3 = __shfl_xor_sync(~0u, a3, off);
            // insert (o1,p1)
            if (o1 < a1 || (o1 == a1 && p1 < b1)) {
                a3 = a2; a2 = a1; b2 = b1; a1 = o1; b1 = p1;
            } else if (o1 < a2 || (o1 == a2 && p1 < b2)) {
                a3 = a2; a2 = o1; b2 = p1;
            } else if (o1 < a3) a3 = o1;
            // insert (o2,p2)  (o2 >= new a1 always)
            if (o2 < a2 || (o2 == a2 && p2 < b2)) {
                a3 = a2; a2 = o2; b2 = p2;
            } else if (o2 < a3) a3 = o2;
            // insert o3 (value only)
            if (o3 < a3) a3 = o3;
        }
        if ((lane & 3) == 0) {
            int token = n0 + (int)Rb + j * 8;
            g_inds[token] = b1;
            float T = 1.0e-3f * sqrtf(znr[j] * enmax) + 6.0e-5f;
            if (a2 - a1 < T) {
                if (a3 - a1 >= T) {
                    int p = atomicAdd(&g_nA, 1);
                    g_listA[p] = token; g_i2a[p] = b2;
                } else {
                    int p = atomicAdd(&g_nB, 1);
                    g_listB[p] = token;
                }
            }
        }
    }
}

// ---------- pairA: exact R1-numerics compare of the two candidate codes ----------
__global__ void __launch_bounds__(256, 1)
vq_pairA(const float* __restrict__ batch, const float* __restrict__ w) {
    const int nA = *(volatile int*)&g_nA;
    for (int k = blockIdx.x * 256 + threadIdx.x; k < nA; k += gridDim.x * 256) {
        int token = g_listA[k];
        int ia = g_inds[token], ib = g_i2a[k];
        const float* zp = batch + (size_t)(token >> 12) * (DIM * 4096) + (token & 4095);
        const float* wa = w + (size_t)ia * DIM;
        const float* wb = w + (size_t)ib * DIM;
        float zn = 0.0f, loa = 0.0f, hia = 0.0f, lob = 0.0f, hib = 0.0f;
        #pragma unroll 4
        for (int c = 0; c < DIM; c += 2) {
            float z0 = zp[(size_t)c * 4096];
            float z1 = zp[(size_t)(c + 1) * 4096];
            zn = __fadd_rn(zn, __fmul_rn(z0, z0));      // R1 znorm chain
            zn = __fadd_rn(zn, __fmul_rn(z1, z1));
            loa = fmaf(z0, wa[c], loa);                 // R1 even-dim chain
            hia = fmaf(z1, wa[c + 1], hia);             // R1 odd-dim chain
            lob = fmaf(z0, wb[c], lob);
            hib = fmaf(z1, wb[c + 1], hib);
        }
        float da = fmaf(-2.0f, __fadd_rn(loa, hia), __fadd_rn(zn, g_enorm[ia]));
        float db = fmaf(-2.0f, __fadd_rn(lob, hib), __fadd_rn(zn, g_enorm[ib]));
        if (db < da || (db == da && ib < ia)) g_inds[token] = ib;
    }
}

// ---------- fullB: verbatim Round-1 numerics full scan for hard tokens ----------
__global__ void __launch_bounds__(256, 1)
vq_fullB(const float* __restrict__ batch, const float* __restrict__ w) {
    const int nf = *(volatile int*)&g_nB;

    extern __shared__ float sm[];
    float* zs = sm;
    float* ws = sm + RT * ZSTR;
    float* zn = ws + R_CHUNK * ZSTR;
    float* en = zn + RT;
    int*   tk = (int*)(en + R_CHUNK);
    int*   tb = tk + RT;
    float* rv = ws;
    int*   ri = (int*)(ws + 512);

    const int tid = threadIdx.x;

    for (int seg = blockIdx.x; seg * RT < nf; seg += gridDim.x) {
        const int base = seg * RT;
        if (tid < RT) {
            int t = (base + tid < nf) ? g_listB[base + tid] : -1;
            tk[tid] = t;
            int tt = (t >= 0) ? t : 0;
            tb[tid] = (tt >> 12) * (DIM * 4096) + (tt & 4095);
        }
        __syncthreads();

        for (int idx = tid; idx < RT * DIM; idx += 256) {
            int t = idx & 15, c = idx >> 4;
            zs[t * ZSTR + c] = batch[(size_t)tb[t] + (size_t)c * 4096];
        }
        __syncthreads();

        if (tid < RT) {
            float s = 0.0f;
            const float* zr = zs + tid * ZSTR;
            #pragma unroll 8
            for (int c = 0; c < DIM; c++)
                s = __fadd_rn(s, __fmul_rn(zr[c], zr[c]));
            zn[tid] = s;
        }
        __syncthreads();

        const int tg = tid & 7;
        const int cg = tid >> 3;
        int zrow[2], wrow[8];
        zrow[0] = tg * ZSTR; zrow[1] = (tg + 8) * ZSTR;
        #pragma unroll
        for (int j = 0; j < 8; j++) wrow[j] = (cg + 32 * j) * ZSTR;
        float znrv[2] = {zn[tg], zn[tg + 8]};

        float bestv[2] = {CUDART_INF_F, CUDART_INF_F};
        int   besti[2] = {0, 0};

        for (int chunk = 0; chunk < R_NCH; chunk++) {
            const int cb = chunk * R_CHUNK;
            __syncthreads();
            for (int f = tid; f < R_CHUNK * 32; f += 256) {
                int code = f >> 5, d4 = f & 31;
                float4 v = ((const float4*)(w + (size_t)(cb + code) * DIM))[d4];
                *(float4*)&ws[code * ZSTR + d4 * 4] = v;
            }
            if (tid < R_CHUNK) en[tid] = g_enorm[cb + tid];
            __syncthreads();

            unsigned long long acc[2][8];
            #pragma unroll
            for (int i = 0; i < 2; i++)
                #pragma unroll
                for (int j = 0; j < 8; j++) acc[i][j] = 0ull;

            #pragma unroll 2
            for (int d4 = 0; d4 < DIM / 4; d4++) {
                unsigned long long za0[2], za1[2];
                #pragma unroll
                for (int i = 0; i < 2; i++) {
                    ulonglong2 v = *(const ulonglong2*)(zs + zrow[i] + d4 * 4);
                    za0[i] = v.x; za1[i] = v.y;
                }
                #pragma unroll
                for (int j = 0; j < 8; j++) {
                    ulonglong2 wv = *(const ulonglong2*)(ws + wrow[j] + d4 * 4);
                    #pragma unroll
                    for (int i = 0; i < 2; i++) {
                        acc[i][j] = ffma2(za0[i], wv.x, acc[i][j]);
                        acc[i][j] = ffma2(za1[i], wv.y, acc[i][j]);
                    }
                }
            }
            #pragma unroll
            for (int j = 0; j < 8; j++) {
                const int code = cb + cg + 32 * j;
                const float ec = en[cg + 32 * j];
                #pragma unroll
                for (int i = 0; i < 2; i++) {
                    float lo, hi;
                    unpack2(acc[i][j], lo, hi);
                    float dot = lo + hi;
                    float s   = znrv[i] + ec;
                    float dis = fmaf(-2.0f, dot, s);
                    if (dis < bestv[i]) { bestv[i] = dis; besti[i] = code; }
                }
            }
        }

        __syncthreads();
        #pragma unroll
        for (int i = 0; i < 2; i++) {
            int t = tg + 8 * i;
            rv[t * 32 + cg] = bestv[i];
            ri[t * 32 + cg] = besti[i];
        }
        __syncthreads();
        if (tid < RT) {
            float bvv = rv[tid * 32];
            int   bii = ri[tid * 32];
            for (int c2 = 1; c2 < 32; c2++) {
                float v = rv[tid * 32 + c2];
                int  ii = ri[tid * 32 + c2];
                if (v < bvv || (v == bvv && ii < bii)) { bvv = v; bii = ii; }
            }
            if (tk[tid] >= 0) g_inds[tk[tid]] = bii;
        }
        __syncthreads();
    }
}

// ---------- output + loss ----------
__global__ void __launch_bounds__(256, 1)
vq_output(const float* __restrict__ batch, const float* __restrict__ w,
          float* __restrict__ out) {
    __shared__ float qsT[128 * 66];
    __shared__ int   si[64];
    __shared__ float red[512];

    const int tid = threadIdx.x, wid = tid >> 5, lane = tid & 31;
    const int n0 = blockIdx.x * 64, b = n0 >> 12, hw0 = n0 & 4095;

    if (tid < 64) si[tid] = g_inds[n0 + tid];
    __syncthreads();

    const float4* w4 = (const float4*)w;
    #pragma unroll
    for (int k = 0; k < 8; k++) {
        int f = tid + k * 256;
        int r = f >> 5, c4 = f & 31;
        float4 v = __ldg(&w4[(size_t)si[r] * 32 + c4]);
        int cb = c4 * 4;
        qsT[(cb + 0) * 66 + r] = v.x;
        qsT[(cb + 1) * 66 + r] = v.y;
        qsT[(cb + 2) * 66 + r] = v.z;
        qsT[(cb + 3) * 66 + r] = v.w;
    }
    __syncthreads();

    float s1 = 0.0f, s3 = 0.0f;
    #pragma unroll 4
    for (int it = 0; it < 16; it++) {
        int c = wid * 16 + it;
        size_t go = ((size_t)(b * 128 + c)) * 4096 + hw0 + 2 * lane;
        float2 z2 = *(const float2*)(batch + go);
        float q0 = qsT[c * 66 + 2 * lane];
        float q1 = qsT[c * 66 + 2 * lane + 1];
        float dq0 = q0 - z2.x, dq1 = q1 - z2.y;
        float ov0 = z2.x + dq0, ov1 = z2.y + dq1;
        float d30 = z2.x - ov0, d31 = z2.y - ov1;
        *(float2*)(out + go) = make_float2(ov0, ov1);
        s1 += dq0 * dq0 + dq1 * dq1;
        s3 += d30 * d30 + d31 * d31;
    }
    red[tid] = s1; red[256 + tid] = s3;
    __syncthreads();
    #pragma unroll
    for (int st = 128; st > 0; st >>= 1) {
        if (tid < st) { red[tid] += red[tid + st]; red[256 + tid] += red[256 + tid + st]; }
        __syncthreads();
    }
    if (tid == 0) {
        atomicAdd(&g_s1, (double)red[0]);
        atomicAdd(&g_s3, (double)red[256]);
    }
}

// ---------- finalize ----------
__global__ void vq_finalize(float* __restrict__ out, int out_size) {
    if (out_size <= TOT_ELEMS) return;
    const double inv = 1.0 / (double)TOT_ELEMS;
    float t1 = (float)(g_s1 * inv);
    float t3 = (float)(g_s3 * inv);
    out[TOT_ELEMS] = (t1 + t1) + t3 * 50.0f;
}

// ---------- launch ----------
extern "C" void kernel_launch(void* const* d_in, const int* in_sizes, int n_in,
                              void* d_out, int out_size) {
    const float* batch = (const float*)d_in[0];
    const float* wq    = (const float*)d_in[1];
    if (n_in >= 2 && in_sizes[0] == NUM_CODES * DIM) {
        const float* t = batch; batch = wq; wq = t;
    }
    float* out = (float*)d_out;

    const int SMEM_RECHECK = (RT * ZSTR + R_CHUNK * ZSTR + RT + R_CHUNK) * 4 + 128;

    cudaFuncSetAttribute(vq_tensor, cudaFuncAttributeMaxDynamicSharedMemorySize,
                         SMEM_TENSOR);
    cudaFuncSetAttribute(vq_fullB, cudaFuncAttributeMaxDynamicSharedMemorySize,
                         SMEM_RECHECK);

    vq_prep<<<320, 256>>>(wq);
    vq_tensor<<<N_TOKENS / TPC, 256, SMEM_TENSOR>>>(batch);
    vq_pairA<<<64, 256>>>(batch, wq);
    vq_fullB<<<512, 256, SMEM_RECHECK>>>(batch, wq);
    vq_output<<<N_TOKENS / 64, 256>>>(batch, wq, out);
    vq_finalize<<<1, 1>>>(out, out_size);
}